// round 1
// baseline (speedup 1.0000x reference)
#include <cuda_runtime.h>
#include <cstdint>

// SPLoPAdapter: out[i*32+a, j*32+b] = weights[.] + sum_k pos[k,i,j]*w[k,a]*h[k,b]
// Shapes: weights (2048,2048) f32; pos (64,64,64); proto_w (64,32,1); proto_h (64,1,32)

#define FMA2(acc, av, bv) \
    asm("fma.rn.f32x2 %0, %1, %2, %3;" : "=l"(acc) : "l"(av), "l"(bv), "l"(acc))

__global__ void __launch_bounds__(256) splopa_kernel(
    const float* __restrict__ weights,
    const float* __restrict__ pos,
    const float* __restrict__ pw,
    const float* __restrict__ ph,
    float* __restrict__ out)
{
    // 4 tiles per CTA (2x2 group of 32x32 output tiles)
    __shared__ float sw[4][64][32];   // sw[t][k][a] = pos[k,i_t,j_t] * w[k,a]  (32 KB)
    __shared__ float hs[64][32];      // h[k][b]                                (8 KB)
    __shared__ float ps[4][64];       // pos per tile                           (1 KB)

    const int tid = threadIdx.x;
    const int i0 = blockIdx.y << 1;   // tile-row base (0..62 step 2)
    const int j0 = blockIdx.x << 1;   // tile-col base

    // load h (64x32 contiguous floats)
    #pragma unroll
    for (int idx = tid; idx < 2048; idx += 256)
        ((float*)hs)[idx] = ph[idx];

    // load pos for the 4 tiles: tile t = (ti,tj) = (t>>1, t&1)
    {
        const int t = tid >> 6;
        const int k = tid & 63;
        ps[t][k] = pos[k * 4096 + (i0 + (t >> 1)) * 64 + (j0 + (t & 1))];
    }
    __syncthreads();

    // build sw[t][k][a] = ps[t][k] * w[k,a]
    #pragma unroll
    for (int idx = tid; idx < 8192; idx += 256) {
        const int t  = idx >> 11;
        const int ka = idx & 2047;           // ka = k*32 + a
        ((float*)sw[t])[ka] = ps[t][ka >> 5] * pw[ka];
    }
    __syncthreads();

    // Each thread: one tile t, 4x4 output patch (aq selects 4 rows, bq 4 cols)
    const int t    = tid >> 6;
    const int wtid = tid & 63;
    const int aq   = wtid >> 3;              // 0..7
    const int bq   = wtid & 7;               // 0..7

    const float* swp = &sw[t][0][0] + aq * 4;
    const float* hpp = &hs[0][0]    + bq * 4;

    unsigned long long acc[4][2];
    #pragma unroll
    for (int a = 0; a < 4; a++) { acc[a][0] = 0ull; acc[a][1] = 0ull; }

    #pragma unroll 8
    for (int k = 0; k < 64; k++) {
        const float4 s4 = *(const float4*)(swp + k * 32);       // sw[k][a0..a3]
        const ulonglong2 h2 = *(const ulonglong2*)(hpp + k * 32); // h[k][b0..b3] as 2x f32x2

        unsigned long long d0, d1, d2, d3;
        asm("mov.b64 %0, {%1, %1};" : "=l"(d0) : "r"(__float_as_uint(s4.x)));
        asm("mov.b64 %0, {%1, %1};" : "=l"(d1) : "r"(__float_as_uint(s4.y)));
        asm("mov.b64 %0, {%1, %1};" : "=l"(d2) : "r"(__float_as_uint(s4.z)));
        asm("mov.b64 %0, {%1, %1};" : "=l"(d3) : "r"(__float_as_uint(s4.w)));

        FMA2(acc[0][0], d0, h2.x); FMA2(acc[0][1], d0, h2.y);
        FMA2(acc[1][0], d1, h2.x); FMA2(acc[1][1], d1, h2.y);
        FMA2(acc[2][0], d2, h2.x); FMA2(acc[2][1], d2, h2.y);
        FMA2(acc[3][0], d3, h2.x); FMA2(acc[3][1], d3, h2.y);
    }

    // epilogue: out = weights + acc
    const int row0 = (i0 + (t >> 1)) * 32 + aq * 4;
    const int col0 = (j0 + (t & 1)) * 32 + bq * 4;

    #pragma unroll
    for (int a = 0; a < 4; a++) {
        const size_t off = (size_t)(row0 + a) * 2048 + col0;
        const ulonglong2 wv = *(const ulonglong2*)(weights + off);
        ulonglong2 ov;
        asm("add.rn.f32x2 %0, %1, %2;" : "=l"(ov.x) : "l"(wv.x), "l"(acc[a][0]));
        asm("add.rn.f32x2 %0, %1, %2;" : "=l"(ov.y) : "l"(wv.y), "l"(acc[a][1]));
        *(ulonglong2*)(out + off) = ov;
    }
}

extern "C" void kernel_launch(void* const* d_in, const int* in_sizes, int n_in,
                              void* d_out, int out_size)
{
    const float* weights = (const float*)d_in[0];
    const float* pos     = (const float*)d_in[1];
    const float* pw      = (const float*)d_in[2];
    const float* ph      = (const float*)d_in[3];
    float* out           = (float*)d_out;

    dim3 grid(32, 32);   // 2x2 tiles of 32x32 per CTA over a 64x64 tile grid
    dim3 block(256);
    splopa_kernel<<<grid, block>>>(weights, pos, pw, ph, out);
}